// round 2
// baseline (speedup 1.0000x reference)
#include <cuda_runtime.h>
#include <cuda_bf16.h>
#include <math.h>

// EMDLoss: mean over (b,n) of min_m ||pred[b,n]-target[b,m]||_2
// B=32, N=4096, M=4096, dim=3.
// d2 = p2 + (t2 - 2 p.t); min over m of (t2 - 2 p.t), add p2, clamp, sqrt.
// Inner loop: 3 FFMA + 1 FMNMX per pair. Targets staged in smem as float4(x,y,z,t2).

#define EMD_B 32
#define EMD_N 4096
#define EMD_M 4096
#define TILE_M 2048
#define THREADS 256

__global__ void __launch_bounds__(THREADS)
emd_min_kernel(const float* __restrict__ pred,
               const float* __restrict__ target,
               float* __restrict__ out)
{
    __shared__ float4 smt[TILE_M];          // 32 KB
    __shared__ float wsum[THREADS / 32];

    const int g = blockIdx.x * THREADS + threadIdx.x;   // global pred index, 0..B*N-1
    const int b = g >> 12;                              // N = 4096

    // Load this thread's pred point
    const float* pp = pred + (size_t)g * 3;
    const float px = pp[0], py = pp[1], pz = pp[2];
    const float qx = -2.0f * px, qy = -2.0f * py, qz = -2.0f * pz;
    const float p2 = fmaf(px, px, fmaf(py, py, pz * pz));

    float m0 = 3.4e38f, m1 = 3.4e38f;       // two accumulators to break the min dep-chain

    const float* tb = target + (size_t)b * EMD_M * 3;

    for (int tile = 0; tile < EMD_M; tile += TILE_M) {
        __syncthreads();   // previous tile fully consumed before overwrite
        // Stage TILE_M targets as (x, y, z, |t|^2)
        for (int j = threadIdx.x; j < TILE_M; j += THREADS) {
            const float* tp = tb + (size_t)(tile + j) * 3;
            const float tx = tp[0], ty = tp[1], tz = tp[2];
            smt[j] = make_float4(tx, ty, tz, fmaf(tx, tx, fmaf(ty, ty, tz * tz)));
        }
        __syncthreads();

        #pragma unroll 8
        for (int j = 0; j < TILE_M; j += 2) {
            const float4 t0 = smt[j];
            const float4 t1 = smt[j + 1];
            const float s0 = fmaf(qx, t0.x, fmaf(qy, t0.y, fmaf(qz, t0.z, t0.w)));
            const float s1 = fmaf(qx, t1.x, fmaf(qy, t1.y, fmaf(qz, t1.z, t1.w)));
            m0 = fminf(m0, s0);
            m1 = fminf(m1, s1);
        }
    }

    const float smin = fminf(m0, m1);
    const float d = sqrtf(fmaxf(p2 + smin, 0.0f));
    float val = d * (1.0f / ((float)EMD_B * (float)EMD_N));

    // Warp reduction
    #pragma unroll
    for (int o = 16; o; o >>= 1)
        val += __shfl_xor_sync(0xffffffffu, val, o);

    if ((threadIdx.x & 31) == 0)
        wsum[threadIdx.x >> 5] = val;
    __syncthreads();

    if (threadIdx.x < (THREADS / 32)) {
        float v = wsum[threadIdx.x];
        #pragma unroll
        for (int o = (THREADS / 64); o; o >>= 1)
            v += __shfl_xor_sync(0xffu, v, o);
        if (threadIdx.x == 0)
            atomicAdd(out, v);
    }
}

extern "C" void kernel_launch(void* const* d_in, const int* in_sizes, int n_in,
                              void* d_out, int out_size)
{
    const float* pred   = (const float*)d_in[0];
    const float* target = (const float*)d_in[1];
    float* out = (float*)d_out;

    cudaMemsetAsync(out, 0, sizeof(float));

    const int total = EMD_B * EMD_N;                 // 131072 pred points
    const int blocks = total / THREADS;              // 512
    emd_min_kernel<<<blocks, THREADS>>>(pred, target, out);
}

// round 3
// speedup vs baseline: 1.6149x; 1.6149x over previous
#include <cuda_runtime.h>
#include <cuda_bf16.h>
#include <math.h>

// EMDLoss: mean over (b,n) of min_m ||pred[b,n]-target[b,m]||, B=32, N=M=4096, d=3.
// s = t2 - 2 p.t  (min over m preserves ordering of d2 = p2 + s).
// Kernel 1: packed f32x2 FFMA over pred-pairs; targets staged duplicated in smem.
// Kernel 2: cross-slice min + sqrt + mean reduction.

#define EMD_B 32
#define EMD_N 4096
#define EMD_M 4096

#define THREADS 256
#define PPT 4                 // pred points per thread
#define PREDS_PER_BLK (THREADS * PPT)        // 1024
#define NUM_CHUNKS (EMD_B * EMD_N / PREDS_PER_BLK)   // 128
#define NSLICES 8
#define SLICE (EMD_M / NSLICES)              // 512 targets per block

__device__ float g_partial[NSLICES][EMD_B * EMD_N];   // 4 MB scratch

__device__ __forceinline__ unsigned long long ffma2(unsigned long long a,
                                                    unsigned long long b,
                                                    unsigned long long c)
{
    unsigned long long d;
    asm("fma.rn.f32x2 %0, %1, %2, %3;" : "=l"(d) : "l"(a), "l"(b), "l"(c));
    return d;
}

__device__ __forceinline__ unsigned long long pack2(float lo, float hi)
{
    unsigned long long r;
    asm("mov.b64 %0, {%1, %2};" : "=l"(r) : "f"(lo), "f"(hi));
    return r;
}

__device__ __forceinline__ float lo2(unsigned long long v)
{
    return __uint_as_float((unsigned)v);
}
__device__ __forceinline__ float hi2(unsigned long long v)
{
    return __uint_as_float((unsigned)(v >> 32));
}

__global__ void __launch_bounds__(THREADS)
emd_partial_kernel(const float* __restrict__ pred,
                   const float* __restrict__ target)
{
    // smem: per target two float4s: (x,x,y,y) and (z,z,t2,t2)  -> 16 KB
    __shared__ float4 smt[SLICE * 2];

    const int chunk = blockIdx.x & (NUM_CHUNKS - 1);
    const int slice = blockIdx.x >> 7;              // NUM_CHUNKS = 128
    const int base  = chunk * PREDS_PER_BLK;        // all preds in this block share batch b
    const int b     = base >> 12;                   // N = 4096

    // Load PPT pred points, pack q = -2p into f32x2 pairs
    float px[PPT], py[PPT], pz[PPT];
    #pragma unroll
    for (int k = 0; k < PPT; k++) {
        const float* pp = pred + (size_t)(base + threadIdx.x + k * THREADS) * 3;
        px[k] = pp[0]; py[k] = pp[1]; pz[k] = pp[2];
    }
    const unsigned long long qx01 = pack2(-2.0f * px[0], -2.0f * px[1]);
    const unsigned long long qy01 = pack2(-2.0f * py[0], -2.0f * py[1]);
    const unsigned long long qz01 = pack2(-2.0f * pz[0], -2.0f * pz[1]);
    const unsigned long long qx23 = pack2(-2.0f * px[2], -2.0f * px[3]);
    const unsigned long long qy23 = pack2(-2.0f * py[2], -2.0f * py[3]);
    const unsigned long long qz23 = pack2(-2.0f * pz[2], -2.0f * pz[3]);

    // Stage this block's target slice, duplicated components
    const float* tb = target + (size_t)(b * EMD_M + slice * SLICE) * 3;
    for (int j = threadIdx.x; j < SLICE; j += THREADS) {
        const float* tp = tb + (size_t)j * 3;
        const float tx = tp[0], ty = tp[1], tz = tp[2];
        const float t2 = fmaf(tx, tx, fmaf(ty, ty, tz * tz));
        smt[2 * j]     = make_float4(tx, tx, ty, ty);
        smt[2 * j + 1] = make_float4(tz, tz, t2, t2);
    }
    __syncthreads();

    float m0 = 3.4e38f, m1 = 3.4e38f, m2 = 3.4e38f, m3 = 3.4e38f;

    const ulonglong2* smtu = (const ulonglong2*)smt;

    #pragma unroll 8
    for (int j = 0; j < SLICE; j++) {
        const ulonglong2 v0 = smtu[2 * j];       // (x,x), (y,y)
        const ulonglong2 v1 = smtu[2 * j + 1];   // (z,z), (t2,t2)
        const unsigned long long s01 =
            ffma2(qx01, v0.x, ffma2(qy01, v0.y, ffma2(qz01, v1.x, v1.y)));
        const unsigned long long s23 =
            ffma2(qx23, v0.x, ffma2(qy23, v0.y, ffma2(qz23, v1.x, v1.y)));
        m0 = fminf(m0, lo2(s01));
        m1 = fminf(m1, hi2(s01));
        m2 = fminf(m2, lo2(s23));
        m3 = fminf(m3, hi2(s23));
    }

    float* gp = g_partial[slice];
    gp[base + threadIdx.x + 0 * THREADS] = m0;
    gp[base + threadIdx.x + 1 * THREADS] = m1;
    gp[base + threadIdx.x + 2 * THREADS] = m2;
    gp[base + threadIdx.x + 3 * THREADS] = m3;
}

__global__ void __launch_bounds__(THREADS)
emd_reduce_kernel(const float* __restrict__ pred,
                  float* __restrict__ out)
{
    __shared__ float wsum[THREADS / 32];

    const int i = blockIdx.x * THREADS + threadIdx.x;

    float m = g_partial[0][i];
    #pragma unroll
    for (int s = 1; s < NSLICES; s++)
        m = fminf(m, g_partial[s][i]);

    const float* pp = pred + (size_t)i * 3;
    const float px = pp[0], py = pp[1], pz = pp[2];
    const float p2 = fmaf(px, px, fmaf(py, py, pz * pz));

    const float d = sqrtf(fmaxf(p2 + m, 0.0f));
    float val = d * (1.0f / ((float)EMD_B * (float)EMD_N));

    #pragma unroll
    for (int o = 16; o; o >>= 1)
        val += __shfl_xor_sync(0xffffffffu, val, o);
    if ((threadIdx.x & 31) == 0)
        wsum[threadIdx.x >> 5] = val;
    __syncthreads();

    if (threadIdx.x < (THREADS / 32)) {
        float v = wsum[threadIdx.x];
        #pragma unroll
        for (int o = (THREADS / 64); o; o >>= 1)
            v += __shfl_xor_sync(0xffu, v, o);
        if (threadIdx.x == 0)
            atomicAdd(out, v);
    }
}

extern "C" void kernel_launch(void* const* d_in, const int* in_sizes, int n_in,
                              void* d_out, int out_size)
{
    const float* pred   = (const float*)d_in[0];
    const float* target = (const float*)d_in[1];
    float* out = (float*)d_out;

    cudaMemsetAsync(out, 0, sizeof(float));

    emd_partial_kernel<<<NUM_CHUNKS * NSLICES, THREADS>>>(pred, target);
    emd_reduce_kernel<<<EMD_B * EMD_N / THREADS, THREADS>>>(pred, out);
}

// round 4
// speedup vs baseline: 1.6200x; 1.0032x over previous
#include <cuda_runtime.h>
#include <cuda_bf16.h>
#include <math.h>

// EMDLoss: mean over (b,n) of min_m ||pred[b,n]-target[b,m]||, B=32, N=M=4096, d=3.
// s = t2 - 2 p.t ; min_m s preserves ordering of d2 = p2 + s.
// Kernel 1: 8 pred points/thread, packed f32x2 FFMA; targets staged duplicated in smem.
// Kernel 2: cross-slice min + sqrt + mean.

#define EMD_B 32
#define EMD_N 4096
#define EMD_M 4096

#define THREADS 256
#define PPT 8
#define PREDS_PER_BLK (THREADS * PPT)                  // 2048
#define NUM_CHUNKS (EMD_B * EMD_N / PREDS_PER_BLK)    // 64
#define NSLICES 16
#define SLICE (EMD_M / NSLICES)                        // 256 targets per block

__device__ float g_partial[NSLICES][EMD_B * EMD_N];    // 8 MB scratch

__device__ __forceinline__ unsigned long long ffma2(unsigned long long a,
                                                    unsigned long long b,
                                                    unsigned long long c)
{
    unsigned long long d;
    asm("fma.rn.f32x2 %0, %1, %2, %3;" : "=l"(d) : "l"(a), "l"(b), "l"(c));
    return d;
}

__device__ __forceinline__ unsigned long long pack2(float lo, float hi)
{
    unsigned long long r;
    asm("mov.b64 %0, {%1, %2};" : "=l"(r) : "f"(lo), "f"(hi));
    return r;
}

__device__ __forceinline__ float lo2(unsigned long long v)
{
    return __uint_as_float((unsigned)v);
}
__device__ __forceinline__ float hi2(unsigned long long v)
{
    return __uint_as_float((unsigned)(v >> 32));
}

__global__ void __launch_bounds__(THREADS)
emd_partial_kernel(const float* __restrict__ pred,
                   const float* __restrict__ target)
{
    // per target two float4s: (x,x,y,y) and (z,z,t2,t2)  -> 8 KB
    __shared__ float4 smt[SLICE * 2];

    const int chunk = blockIdx.x & (NUM_CHUNKS - 1);
    const int slice = blockIdx.x >> 6;                 // NUM_CHUNKS = 64
    const int base  = chunk * PREDS_PER_BLK;           // all preds share batch b
    const int b     = base >> 12;                      // N = 4096

    // Load PPT pred points, pack q = -2p into f32x2 pairs
    float px[PPT], py[PPT], pz[PPT];
    #pragma unroll
    for (int k = 0; k < PPT; k++) {
        const float* pp = pred + (size_t)(base + threadIdx.x + k * THREADS) * 3;
        px[k] = pp[0]; py[k] = pp[1]; pz[k] = pp[2];
    }
    unsigned long long qx[PPT / 2], qy[PPT / 2], qz[PPT / 2];
    #pragma unroll
    for (int k = 0; k < PPT / 2; k++) {
        qx[k] = pack2(-2.0f * px[2 * k], -2.0f * px[2 * k + 1]);
        qy[k] = pack2(-2.0f * py[2 * k], -2.0f * py[2 * k + 1]);
        qz[k] = pack2(-2.0f * pz[2 * k], -2.0f * pz[2 * k + 1]);
    }

    // Stage this block's target slice, duplicated components
    const float* tb = target + (size_t)(b * EMD_M + slice * SLICE) * 3;
    for (int j = threadIdx.x; j < SLICE; j += THREADS) {
        const float* tp = tb + (size_t)j * 3;
        const float tx = tp[0], ty = tp[1], tz = tp[2];
        const float t2 = fmaf(tx, tx, fmaf(ty, ty, tz * tz));
        smt[2 * j]     = make_float4(tx, tx, ty, ty);
        smt[2 * j + 1] = make_float4(tz, tz, t2, t2);
    }
    __syncthreads();

    float mn[PPT];
    #pragma unroll
    for (int k = 0; k < PPT; k++) mn[k] = 3.4e38f;

    const ulonglong2* smtu = (const ulonglong2*)smt;

    #pragma unroll 4
    for (int j = 0; j < SLICE; j++) {
        const ulonglong2 v0 = smtu[2 * j];       // (x,x), (y,y)
        const ulonglong2 v1 = smtu[2 * j + 1];   // (z,z), (t2,t2)
        #pragma unroll
        for (int k = 0; k < PPT / 2; k++) {
            const unsigned long long s =
                ffma2(qx[k], v0.x, ffma2(qy[k], v0.y, ffma2(qz[k], v1.x, v1.y)));
            mn[2 * k]     = fminf(mn[2 * k],     lo2(s));
            mn[2 * k + 1] = fminf(mn[2 * k + 1], hi2(s));
        }
    }

    float* gp = g_partial[slice] + base + threadIdx.x;
    #pragma unroll
    for (int k = 0; k < PPT; k++)
        gp[k * THREADS] = mn[k];
}

__global__ void __launch_bounds__(THREADS)
emd_reduce_kernel(const float* __restrict__ pred,
                  float* __restrict__ out)
{
    __shared__ float wsum[THREADS / 32];

    const int i = blockIdx.x * THREADS + threadIdx.x;

    float m = g_partial[0][i];
    #pragma unroll
    for (int s = 1; s < NSLICES; s++)
        m = fminf(m, g_partial[s][i]);

    const float* pp = pred + (size_t)i * 3;
    const float px = pp[0], py = pp[1], pz = pp[2];
    const float p2 = fmaf(px, px, fmaf(py, py, pz * pz));

    const float d = sqrtf(fmaxf(p2 + m, 0.0f));
    float val = d * (1.0f / ((float)EMD_B * (float)EMD_N));

    #pragma unroll
    for (int o = 16; o; o >>= 1)
        val += __shfl_xor_sync(0xffffffffu, val, o);
    if ((threadIdx.x & 31) == 0)
        wsum[threadIdx.x >> 5] = val;
    __syncthreads();

    if (threadIdx.x < (THREADS / 32)) {
        float v = wsum[threadIdx.x];
        #pragma unroll
        for (int o = (THREADS / 64); o; o >>= 1)
            v += __shfl_xor_sync(0xffu, v, o);
        if (threadIdx.x == 0)
            atomicAdd(out, v);
    }
}

extern "C" void kernel_launch(void* const* d_in, const int* in_sizes, int n_in,
                              void* d_out, int out_size)
{
    const float* pred   = (const float*)d_in[0];
    const float* target = (const float*)d_in[1];
    float* out = (float*)d_out;

    cudaMemsetAsync(out, 0, sizeof(float));

    emd_partial_kernel<<<NUM_CHUNKS * NSLICES, THREADS>>>(pred, target);
    emd_reduce_kernel<<<EMD_B * EMD_N / THREADS, THREADS>>>(pred, out);
}